// round 13
// baseline (speedup 1.0000x reference)
#include <cuda_runtime.h>
#include <cuda_bf16.h>
#include <cstdint>
#include <cstddef>

// ---------------------------------------------------------------------------
// out[s,o] = sum_r lambda[s,r] * sigmoid( X[s,:] . W[r*512+o,:] + b[r*512+o] )
// S=8192, K=1024, R=16, O=512.
//
// bf16 HMMA (mma.sync.m16n8k16).
// R13: ILP experiment in the R7-proven resource shape.
//   CTA 256 thr / 8 warps, tile 128x128, warp tile 64x32 (2x4), BK=64,
//   4-stage cp.async pipeline (128KB smem), one __syncthreads per iter,
//   double-buffered ldmatrix fragments (MMA:ldsm = 2.67, 16 indep chains).
//   launch_bounds(256,1) -> 255-reg budget (R7 shape: 221 regs, no spills).
//   Grid 256 = 64 S-tiles x 4 O-tiles.
// ---------------------------------------------------------------------------

#define BM 128
#define BN 128
#define BK 64
#define STAGES 4
#define ROWB 128                           // bytes per smem row (BK*2)
#define A_BYTES (BM * ROWB)                // 16384
#define B_BYTES (BN * ROWB)                // 16384
#define STAGE_BYTES (A_BYTES + B_BYTES)    // 32768
#define SMEM_BYTES (STAGES * STAGE_BYTES)  // 131072
#define NITER 256                          // 16 rules * 16 k-chunks

__device__ __align__(16) __nv_bfloat16 gXbf[8388608];   // 8192 x 1024
__device__ __align__(16) __nv_bfloat16 gWbf[8388608];   // 8192 x 1024

// ------------------------------ PTX helpers --------------------------------
static __device__ __forceinline__ uint32_t smem_u32(const void* p) {
    uint32_t a;
    asm("{ .reg .u64 t; cvta.to.shared.u64 t, %1; cvt.u32.u64 %0, t; }"
        : "=r"(a) : "l"(p));
    return a;
}
static __device__ __forceinline__ void cpa16(uint32_t dst, const void* src) {
    asm volatile("cp.async.cg.shared.global [%0], [%1], 16;"
                 :: "r"(dst), "l"(src) : "memory");
}
static __device__ __forceinline__ void cp_commit() {
    asm volatile("cp.async.commit_group;" ::: "memory");
}
template <int N> static __device__ __forceinline__ void cp_wait() {
    asm volatile("cp.async.wait_group %0;" :: "n"(N) : "memory");
}
static __device__ __forceinline__ void ldsm4(uint32_t& r0, uint32_t& r1,
                                             uint32_t& r2, uint32_t& r3,
                                             uint32_t addr) {
    asm volatile("ldmatrix.sync.aligned.m8n8.x4.shared.b16 {%0,%1,%2,%3}, [%4];"
                 : "=r"(r0), "=r"(r1), "=r"(r2), "=r"(r3) : "r"(addr));
}
static __device__ __forceinline__ void mma16816(
    float& c0, float& c1, float& c2, float& c3,
    uint32_t a0, uint32_t a1, uint32_t a2, uint32_t a3,
    uint32_t b0, uint32_t b1) {
    asm volatile(
        "mma.sync.aligned.m16n8k16.row.col.f32.bf16.bf16.f32 "
        "{%0,%1,%2,%3}, {%4,%5,%6,%7}, {%8,%9}, {%0,%1,%2,%3};"
        : "+f"(c0), "+f"(c1), "+f"(c2), "+f"(c3)
        : "r"(a0), "r"(a1), "r"(a2), "r"(a3), "r"(b0), "r"(b1));
}

// --------------------------- fp32 -> bf16 pack -----------------------------
__global__ void pack_kernel(const float* __restrict__ X,
                            const float* __restrict__ W) {
    unsigned q = blockIdx.x * blockDim.x + threadIdx.x;  // 2^21 threads exactly
    const float4* src;
    uint4* dst;
    if (q < (1u << 20)) {
        src = reinterpret_cast<const float4*>(X) + (size_t)q * 2;
        dst = reinterpret_cast<uint4*>(gXbf) + q;
    } else {
        unsigned p = q - (1u << 20);
        src = reinterpret_cast<const float4*>(W) + (size_t)p * 2;
        dst = reinterpret_cast<uint4*>(gWbf) + p;
    }
    float4 v0 = src[0];
    float4 v1 = src[1];
    __nv_bfloat162 b0 = __floats2bfloat162_rn(v0.x, v0.y);
    __nv_bfloat162 b1 = __floats2bfloat162_rn(v0.z, v0.w);
    __nv_bfloat162 b2 = __floats2bfloat162_rn(v1.x, v1.y);
    __nv_bfloat162 b3 = __floats2bfloat162_rn(v1.z, v1.w);
    uint4 o;
    o.x = *reinterpret_cast<unsigned*>(&b0);
    o.y = *reinterpret_cast<unsigned*>(&b1);
    o.z = *reinterpret_cast<unsigned*>(&b2);
    o.w = *reinterpret_cast<unsigned*>(&b3);
    *dst = o;
}

// ------------------------------- main kernel -------------------------------
__global__ void __launch_bounds__(256, 1) somfnn_main(
    const float* __restrict__ bias,      // [8192] = [16 rules x 512]
    const float* __restrict__ lambdas,   // [8192 x 16]
    float* __restrict__ out)             // [8192 x 512]
{
    extern __shared__ __align__(128) unsigned char smem[];
    const uint32_t sb = smem_u32(smem);

    const int tid  = threadIdx.x;
    const int lane = tid & 31;
    const int wid  = tid >> 5;           // 0..7
    const int st   = blockIdx.x >> 2;    // S-tile 0..63
    const int ot   = blockIdx.x & 3;     // O-tile 0..3
    const int wm   = wid >> 2;           // 0..1 -> rows wm*64
    const int wn   = wid & 3;            // 0..3 -> cols wn*32

    // ---- loader mapping (R7-proven): thread t -> row t>>1, 4 x 16B chunks --
    const int ldrow = tid >> 1;                 // 0..127
    const int ldc0  = (tid & 1) * 4;            // chunk base 0 or 4 (of 8)
    const uint32_t lswz = (uint32_t)(ldrow & 7);
    const __nv_bfloat16* aG = gXbf + (size_t)(st * 128 + ldrow) * 1024;
    const __nv_bfloat16* bG = gWbf + (size_t)(ot * 128 + ldrow) * 1024;
    const uint32_t aDst = sb + (uint32_t)ldrow * ROWB;
    const uint32_t bDst = sb + A_BYTES + (uint32_t)ldrow * ROWB;

    auto load_stage = [&](int itL, int s) {
        const int rule = itL >> 4;
        const int kt   = itL & 15;
        const __nv_bfloat16* as = aG + kt * 64 + ldc0 * 8;
        const __nv_bfloat16* bs = bG + (size_t)rule * 524288 + kt * 64 + ldc0 * 8;
        const uint32_t ab = aDst + (uint32_t)s * STAGE_BYTES;
        const uint32_t bb = bDst + (uint32_t)s * STAGE_BYTES;
#pragma unroll
        for (int j = 0; j < 4; j++) {
            const uint32_t off = (((uint32_t)(ldc0 + j) ^ lswz) * 16u);
            cpa16(ab + off, as + j * 8);
            cpa16(bb + off, bs + j * 8);
        }
    };

    // ---- ldmatrix per-lane invariants (R7-proven formulas) ----
    const int laneLo = lane & 15;
    const int laneHi = lane >> 4;
    const uint32_t aRow = (uint32_t)(wm * 64 + laneLo);
    const uint32_t aOff = aRow * ROWB;
    const uint32_t sA   = aRow & 7;
    const uint32_t bRow = (uint32_t)(wn * 32 + ((lane >> 4) << 3) + (lane & 7));
    const uint32_t bOff = bRow * ROWB;
    const uint32_t sB   = bRow & 7;
    const uint32_t bCLo = (uint32_t)((lane >> 3) & 1);

    float acc[4][4][4];   // current-rule accumulators (warp tile 64x32)
    float oac[4][4][4];   // lambda-weighted output accumulators
#pragma unroll
    for (int mi = 0; mi < 4; mi++)
#pragma unroll
        for (int nj = 0; nj < 4; nj++)
#pragma unroll
            for (int q = 0; q < 4; q++) { acc[mi][nj][q] = 0.f; oac[mi][nj][q] = 0.f; }

    const int rowL = lane >> 2;
    const int colL = 2 * (lane & 3);

    // fragment double buffers
    uint32_t afr[2][4][4];
    uint32_t bfr[2][4][2];

    auto ld_afrag = [&](uint32_t As, int ks, int buf) {
#pragma unroll
        for (int mi = 0; mi < 4; mi++) {
            const uint32_t addr = As + aOff + (uint32_t)(mi * 16 * ROWB)
                                + (((uint32_t)(ks * 2 + laneHi) ^ sA) * 16u);
            ldsm4(afr[buf][mi][0], afr[buf][mi][1],
                  afr[buf][mi][2], afr[buf][mi][3], addr);
        }
    };
    auto ld_bfrag = [&](uint32_t Bs, int ks, int buf) {
#pragma unroll
        for (int nh = 0; nh < 2; nh++) {
            const uint32_t addr = Bs + bOff + (uint32_t)(nh * 16 * ROWB)
                                + ((((uint32_t)(ks * 2) + bCLo) ^ sB) * 16u);
            uint32_t r0, r1, r2, r3;
            ldsm4(r0, r1, r2, r3, addr);
            bfr[buf][nh * 2][0] = r0;     bfr[buf][nh * 2][1] = r1;
            bfr[buf][nh * 2 + 1][0] = r2; bfr[buf][nh * 2 + 1][1] = r3;
        }
    };

    // ---- prologue: fill stages 0,1,2 ----
    load_stage(0, 0); cp_commit();
    load_stage(1, 1); cp_commit();
    load_stage(2, 2); cp_commit();

    int cs = 0;    // compute slot
    int ls = 3;    // load slot (for it+3)
#pragma unroll 1
    for (int it = 0; it < NITER; it++) {
        cp_wait<2>();                    // compute-stage group complete
        __syncthreads();                 // visible to all; slot ls fully read
        if (it + 3 < NITER) load_stage(it + 3, ls);
        cp_commit();

        const uint32_t As = sb + (uint32_t)cs * STAGE_BYTES;
        const uint32_t Bs = As + A_BYTES;

        // ks-pipelined compute: prefetch frags ks+1 while MMA on ks
        ld_afrag(As, 0, 0);
        ld_bfrag(Bs, 0, 0);
#pragma unroll
        for (int ks = 0; ks < 4; ks++) {
            const int cur = ks & 1;
            const int nxt = cur ^ 1;
            if (ks < 3) {
                ld_afrag(As, ks + 1, nxt);
                ld_bfrag(Bs, ks + 1, nxt);
            }
#pragma unroll
            for (int mi = 0; mi < 4; mi++)
#pragma unroll
                for (int nj = 0; nj < 4; nj++)
                    mma16816(acc[mi][nj][0], acc[mi][nj][1],
                             acc[mi][nj][2], acc[mi][nj][3],
                             afr[cur][mi][0], afr[cur][mi][1],
                             afr[cur][mi][2], afr[cur][mi][3],
                             bfr[cur][nj][0], bfr[cur][nj][1]);
        }

        // ---- per-rule epilogue: sigmoid + lambda-weighted accumulate ----
        if ((it & 15) == 15) {
            const int r = it >> 4;
#pragma unroll
            for (int mi = 0; mi < 4; mi++) {
                const int r0g = st * 128 + wm * 64 + mi * 16 + rowL;
                const float l0 = __ldg(lambdas + (size_t)r0g * 16 + r);
                const float l1 = __ldg(lambdas + (size_t)(r0g + 8) * 16 + r);
#pragma unroll
                for (int nj = 0; nj < 4; nj++) {
                    const int col = ot * 128 + wn * 32 + nj * 8 + colL;
                    const float2 bb = *reinterpret_cast<const float2*>(
                        bias + r * 512 + col);
                    float z0 = acc[mi][nj][0] + bb.x;
                    float z1 = acc[mi][nj][1] + bb.y;
                    float z2 = acc[mi][nj][2] + bb.x;
                    float z3 = acc[mi][nj][3] + bb.y;
                    float s0 = __fdividef(1.f, 1.f + __expf(-z0));
                    float s1 = __fdividef(1.f, 1.f + __expf(-z1));
                    float s2 = __fdividef(1.f, 1.f + __expf(-z2));
                    float s3 = __fdividef(1.f, 1.f + __expf(-z3));
                    oac[mi][nj][0] = fmaf(l0, s0, oac[mi][nj][0]);
                    oac[mi][nj][1] = fmaf(l0, s1, oac[mi][nj][1]);
                    oac[mi][nj][2] = fmaf(l1, s2, oac[mi][nj][2]);
                    oac[mi][nj][3] = fmaf(l1, s3, oac[mi][nj][3]);
                    acc[mi][nj][0] = 0.f; acc[mi][nj][1] = 0.f;
                    acc[mi][nj][2] = 0.f; acc[mi][nj][3] = 0.f;
                }
            }
        }

        cs = (cs == STAGES - 1) ? 0 : cs + 1;
        ls = (ls == STAGES - 1) ? 0 : ls + 1;
    }

    // ---- final store: out tile [128 x 128] fp32 ----
#pragma unroll
    for (int mi = 0; mi < 4; mi++) {
        const int r0g = st * 128 + wm * 64 + mi * 16 + rowL;
#pragma unroll
        for (int nj = 0; nj < 4; nj++) {
            const int col = ot * 128 + wn * 32 + nj * 8 + colL;
            *reinterpret_cast<float2*>(out + (size_t)r0g * 512 + col) =
                make_float2(oac[mi][nj][0], oac[mi][nj][1]);
            *reinterpret_cast<float2*>(out + (size_t)(r0g + 8) * 512 + col) =
                make_float2(oac[mi][nj][2], oac[mi][nj][3]);
        }
    }
}

// ------------------------------- launcher ----------------------------------
extern "C" void kernel_launch(void* const* d_in, const int* in_sizes, int n_in,
                              void* d_out, int out_size) {
    (void)in_sizes; (void)n_in; (void)out_size;
    const float* X   = (const float*)d_in[0];   // [8192,1024]
    const float* W   = (const float*)d_in[1];   // [8192,1024]
    const float* b   = (const float*)d_in[2];   // [8192]
    const float* lam = (const float*)d_in[3];   // [8192,16]
    float* out = (float*)d_out;                 // [8192,512]

    cudaFuncSetAttribute(somfnn_main,
                         cudaFuncAttributeMaxDynamicSharedMemorySize, SMEM_BYTES);

    pack_kernel<<<8192, 256>>>(X, W);
    somfnn_main<<<256, 256, SMEM_BYTES>>>(b, lam, out);
}

// round 14
// speedup vs baseline: 1.7336x; 1.7336x over previous
#include <cuda_runtime.h>
#include <cuda_bf16.h>
#include <cstdint>
#include <cstddef>

// ---------------------------------------------------------------------------
// out[s,o] = sum_r lambda[s,r] * sigmoid( X[s,:] . W[r*512+o,:] + b[r*512+o] )
// S=8192, K=1024, R=16, O=512.
//
// bf16 HMMA (mma.sync.m16n8k16). R14: bulk-copy feed experiment.
//   Compute identical to R9 (tile 128x64, 8 warps of 32x32, BK=64).
//   Load path replaced: pack kernel stores PRE-SWIZZLED contiguous tile
//   blocks; thread 0 issues 2 cp.async.bulk per stage into a 4-stage
//   mbarrier ring (full: tx-based, empty: 256 arrivals). No LDGSTS, no
//   cp_wait convoy, no per-iter __syncthreads.
//   Grid 512 = 64 S-tiles x 8 O-tiles, 2 CTAs/SM.
// ---------------------------------------------------------------------------

#define BM 128
#define BN 64
#define STAGES 4
#define ROWB 128                            // bytes per smem row (BK*2)
#define A_TILE 16384                        // 128 rows x 128B
#define B_TILE 8192                         // 64 rows x 128B
#define STAGE_BYTES (A_TILE + B_TILE)       // 24576
#define TILE_SMEM (STAGES * STAGE_BYTES)    // 98304
#define SMEM_BYTES (TILE_SMEM + 64)
#define NITER 256                           // 16 rules * 16 k-chunks

__device__ __align__(1024) unsigned char gXbf[16777216]; // [st][kt] 16KB blocks
__device__ __align__(1024) unsigned char gWbf[16777216]; // [ot][rule][kt] 8KB blocks

// ------------------------------ PTX helpers --------------------------------
static __device__ __forceinline__ uint32_t smem_u32(const void* p) {
    uint32_t a;
    asm("{ .reg .u64 t; cvta.to.shared.u64 t, %1; cvt.u32.u64 %0, t; }"
        : "=r"(a) : "l"(p));
    return a;
}
static __device__ __forceinline__ void mbar_init(uint32_t m, uint32_t cnt) {
    asm volatile("mbarrier.init.shared.b64 [%0], %1;" :: "r"(m), "r"(cnt) : "memory");
}
static __device__ __forceinline__ void mbar_wait(uint32_t m, uint32_t parity) {
    asm volatile(
        "{\n\t.reg .pred P;\n\t"
        "W_%=:\n\t"
        "mbarrier.try_wait.parity.acquire.cta.shared::cta.b64 P, [%0], %1, 0x989680;\n\t"
        "@!P bra W_%=;\n\t}"
        :: "r"(m), "r"(parity) : "memory");
}
static __device__ __forceinline__ void mbar_arrive(uint32_t m) {
    asm volatile("mbarrier.arrive.shared.b64 _, [%0];" :: "r"(m) : "memory");
}
static __device__ __forceinline__ void mbar_expect_tx(uint32_t m, uint32_t bytes) {
    asm volatile("mbarrier.arrive.expect_tx.shared.b64 _, [%0], %1;"
                 :: "r"(m), "r"(bytes) : "memory");
}
static __device__ __forceinline__ void bulk_g2s(uint32_t dst, const void* src,
                                                uint32_t bytes, uint32_t mbar) {
    asm volatile(
        "cp.async.bulk.shared::cluster.global.mbarrier::complete_tx::bytes "
        "[%0], [%1], %2, [%3];"
        :: "r"(dst), "l"(src), "r"(bytes), "r"(mbar) : "memory");
}
#define FENCE_PA() asm volatile("fence.proxy.async.shared::cta;" ::: "memory")

static __device__ __forceinline__ void ldsm4(uint32_t& r0, uint32_t& r1,
                                             uint32_t& r2, uint32_t& r3,
                                             uint32_t addr) {
    asm volatile("ldmatrix.sync.aligned.m8n8.x4.shared.b16 {%0,%1,%2,%3}, [%4];"
                 : "=r"(r0), "=r"(r1), "=r"(r2), "=r"(r3) : "r"(addr));
}
static __device__ __forceinline__ void mma16816(
    float& c0, float& c1, float& c2, float& c3,
    uint32_t a0, uint32_t a1, uint32_t a2, uint32_t a3,
    uint32_t b0, uint32_t b1) {
    asm volatile(
        "mma.sync.aligned.m16n8k16.row.col.f32.bf16.bf16.f32 "
        "{%0,%1,%2,%3}, {%4,%5,%6,%7}, {%8,%9}, {%0,%1,%2,%3};"
        : "+f"(c0), "+f"(c1), "+f"(c2), "+f"(c3)
        : "r"(a0), "r"(a1), "r"(a2), "r"(a3), "r"(b0), "r"(b1));
}

// --------------- pack: fp32 -> bf16, tiled + PRE-SWIZZLED ------------------
__global__ void pack_kernel(const float* __restrict__ X,
                            const float* __restrict__ W) {
    unsigned q = blockIdx.x * blockDim.x + threadIdx.x;   // 2^21 threads exactly
    const float* src;
    unsigned char* dst;
    if (q < (1u << 20)) {
        // X: q = [st(6)][kt(4)][row(7)][g(3)]
        unsigned g   = q & 7;
        unsigned row = (q >> 3) & 127;
        unsigned kt  = (q >> 10) & 15;
        unsigned st  = q >> 14;
        src = X + ((size_t)(st * 128 + row) * 1024 + kt * 64 + g * 8);
        dst = gXbf + (size_t)(st * 16 + kt) * A_TILE
                   + row * 128 + ((g ^ (row & 7)) << 4);
    } else {
        // W: p = [ot(3)][rule(4)][kt(4)][row(6)][g(3)]
        unsigned p    = q - (1u << 20);
        unsigned g    = p & 7;
        unsigned row  = (p >> 3) & 63;
        unsigned kt   = (p >> 9) & 15;
        unsigned rule = (p >> 13) & 15;
        unsigned ot   = p >> 17;
        src = W + ((size_t)(rule * 512 + ot * 64 + row) * 1024 + kt * 64 + g * 8);
        dst = gWbf + (size_t)((ot * 16 + rule) * 16 + kt) * B_TILE
                   + row * 128 + ((g ^ (row & 7)) << 4);
    }
    float4 v0 = ((const float4*)src)[0];
    float4 v1 = ((const float4*)src)[1];
    __nv_bfloat162 b0 = __floats2bfloat162_rn(v0.x, v0.y);
    __nv_bfloat162 b1 = __floats2bfloat162_rn(v0.z, v0.w);
    __nv_bfloat162 b2 = __floats2bfloat162_rn(v1.x, v1.y);
    __nv_bfloat162 b3 = __floats2bfloat162_rn(v1.z, v1.w);
    uint4 o;
    o.x = *reinterpret_cast<unsigned*>(&b0);
    o.y = *reinterpret_cast<unsigned*>(&b1);
    o.z = *reinterpret_cast<unsigned*>(&b2);
    o.w = *reinterpret_cast<unsigned*>(&b3);
    *reinterpret_cast<uint4*>(dst) = o;
}

// ------------------------------- main kernel -------------------------------
__global__ void __launch_bounds__(256, 2) somfnn_main(
    const float* __restrict__ bias,      // [8192] = [16 rules x 512]
    const float* __restrict__ lambdas,   // [8192 x 16]
    float* __restrict__ out)             // [8192 x 512]
{
    extern __shared__ __align__(128) unsigned char smem[];
    const uint32_t sb = smem_u32(smem);
    const uint32_t mb = sb + TILE_SMEM;      // full[s]=mb+8s, empty[s]=mb+32+8s

    const int tid  = threadIdx.x;
    const int lane = tid & 31;
    const int wid  = tid >> 5;           // 0..7
    const int st   = blockIdx.x >> 3;    // S-tile 0..63
    const int ot   = blockIdx.x & 7;     // O-tile 0..7
    const int wm   = wid >> 1;           // 0..3 -> rows wm*32
    const int wn   = wid & 1;            // 0..1 -> cols wn*32

    if (tid == 0) {
#pragma unroll
        for (int s = 0; s < STAGES; s++) {
            mbar_init(mb + 8 * s, 1);          // full: expect_tx-driven
            mbar_init(mb + 32 + 8 * s, 256);   // empty: all threads arrive
        }
        FENCE_PA();
    }
    __syncthreads();

    const unsigned char* aBase = gXbf + (size_t)st * 16 * A_TILE;
    const unsigned char* bBase = gWbf + (size_t)(ot * 16) * 16 * B_TILE;

    // ---- prologue: thread 0 fills stages 0..2 ----
    if (tid == 0) {
#pragma unroll
        for (int i = 0; i < 3; i++) {
            // itL = i: rule = 0, kt = i
            mbar_expect_tx(mb + 8 * i, STAGE_BYTES);
            bulk_g2s(sb + i * STAGE_BYTES,          aBase + (size_t)i * A_TILE,
                     A_TILE, mb + 8 * i);
            bulk_g2s(sb + i * STAGE_BYTES + A_TILE, bBase + (size_t)i * B_TILE,
                     B_TILE, mb + 8 * i);
        }
    }

    // ---- ldmatrix per-lane invariants (R9-proven formulas) ----
    const int laneLo = lane & 15;
    const int laneHi = lane >> 4;
    const uint32_t aRow = (uint32_t)(wm * 32 + laneLo);
    const uint32_t aOff = aRow * ROWB;
    const uint32_t sA   = aRow & 7;
    const uint32_t bRow = (uint32_t)(wn * 32 + ((lane >> 4) << 3) + (lane & 7));
    const uint32_t bOff = bRow * ROWB;
    const uint32_t sB   = bRow & 7;
    const uint32_t bCLo = (uint32_t)((lane >> 3) & 1);

    float acc[2][4][4];
    float oac[2][4][4];
#pragma unroll
    for (int mi = 0; mi < 2; mi++)
#pragma unroll
        for (int nj = 0; nj < 4; nj++)
#pragma unroll
            for (int q = 0; q < 4; q++) { acc[mi][nj][q] = 0.f; oac[mi][nj][q] = 0.f; }

    const int rowL = lane >> 2;
    const int colL = 2 * (lane & 3);

#pragma unroll 1
    for (int it = 0; it < NITER; it++) {
        const int cs = it & 3;

        // ---- producer: thread 0 refills slot (it+3)&3 ----
        if (tid == 0 && it + 3 < NITER) {
            const int itL = it + 3;
            const int s   = itL & 3;
            mbar_wait(mb + 32 + 8 * s, (((uint32_t)itL >> 2) & 1u) ^ 1u);
            mbar_expect_tx(mb + 8 * s, STAGE_BYTES);
            const int rule = itL >> 4;
            const int kt   = itL & 15;
            bulk_g2s(sb + s * STAGE_BYTES,
                     aBase + (size_t)kt * A_TILE, A_TILE, mb + 8 * s);
            bulk_g2s(sb + s * STAGE_BYTES + A_TILE,
                     bBase + (size_t)(rule * 16 + kt) * B_TILE, B_TILE, mb + 8 * s);
        }

        // ---- consumer: wait for slot cs, compute ----
        mbar_wait(mb + 8 * cs, ((uint32_t)it >> 2) & 1u);

        const uint32_t As = sb + (uint32_t)cs * STAGE_BYTES;
        const uint32_t Bs = As + A_TILE;

#pragma unroll
        for (int ks = 0; ks < 4; ks++) {
            uint32_t a[2][4];
#pragma unroll
            for (int mi = 0; mi < 2; mi++) {
                const uint32_t addr = As + aOff + (uint32_t)(mi * 16 * ROWB)
                                    + (((uint32_t)(ks * 2 + laneHi) ^ sA) * 16u);
                ldsm4(a[mi][0], a[mi][1], a[mi][2], a[mi][3], addr);
            }
            uint32_t b[4][2];
#pragma unroll
            for (int nh = 0; nh < 2; nh++) {
                const uint32_t addr = Bs + bOff + (uint32_t)(nh * 16 * ROWB)
                                    + ((((uint32_t)(ks * 2) + bCLo) ^ sB) * 16u);
                uint32_t r0, r1, r2, r3;
                ldsm4(r0, r1, r2, r3, addr);
                b[nh * 2][0] = r0;     b[nh * 2][1] = r1;
                b[nh * 2 + 1][0] = r2; b[nh * 2 + 1][1] = r3;
            }
#pragma unroll
            for (int mi = 0; mi < 2; mi++)
#pragma unroll
                for (int nj = 0; nj < 4; nj++)
                    mma16816(acc[mi][nj][0], acc[mi][nj][1],
                             acc[mi][nj][2], acc[mi][nj][3],
                             a[mi][0], a[mi][1], a[mi][2], a[mi][3],
                             b[nj][0], b[nj][1]);
        }

        // slot consumed
        mbar_arrive(mb + 32 + 8 * cs);

        // ---- per-rule epilogue: sigmoid + lambda-weighted accumulate ----
        if ((it & 15) == 15) {
            const int r = it >> 4;
#pragma unroll
            for (int mi = 0; mi < 2; mi++) {
                const int r0g = st * 128 + wm * 32 + mi * 16 + rowL;
                const float l0 = __ldg(lambdas + (size_t)r0g * 16 + r);
                const float l1 = __ldg(lambdas + (size_t)(r0g + 8) * 16 + r);
#pragma unroll
                for (int nj = 0; nj < 4; nj++) {
                    const int col = ot * 64 + wn * 32 + nj * 8 + colL;
                    const float2 bb = *reinterpret_cast<const float2*>(
                        bias + r * 512 + col);
                    float z0 = acc[mi][nj][0] + bb.x;
                    float z1 = acc[mi][nj][1] + bb.y;
                    float z2 = acc[mi][nj][2] + bb.x;
                    float z3 = acc[mi][nj][3] + bb.y;
                    float s0 = __fdividef(1.f, 1.f + __expf(-z0));
                    float s1 = __fdividef(1.f, 1.f + __expf(-z1));
                    float s2 = __fdividef(1.f, 1.f + __expf(-z2));
                    float s3 = __fdividef(1.f, 1.f + __expf(-z3));
                    oac[mi][nj][0] = fmaf(l0, s0, oac[mi][nj][0]);
                    oac[mi][nj][1] = fmaf(l0, s1, oac[mi][nj][1]);
                    oac[mi][nj][2] = fmaf(l1, s2, oac[mi][nj][2]);
                    oac[mi][nj][3] = fmaf(l1, s3, oac[mi][nj][3]);
                    acc[mi][nj][0] = 0.f; acc[mi][nj][1] = 0.f;
                    acc[mi][nj][2] = 0.f; acc[mi][nj][3] = 0.f;
                }
            }
        }
    }

    // ---- final store: out tile [128 x 64] fp32 ----
#pragma unroll
    for (int mi = 0; mi < 2; mi++) {
        const int r0g = st * 128 + wm * 32 + mi * 16 + rowL;
#pragma unroll
        for (int nj = 0; nj < 4; nj++) {
            const int col = ot * 64 + wn * 32 + nj * 8 + colL;
            *reinterpret_cast<float2*>(out + (size_t)r0g * 512 + col) =
                make_float2(oac[mi][nj][0], oac[mi][nj][1]);
            *reinterpret_cast<float2*>(out + (size_t)(r0g + 8) * 512 + col) =
                make_float2(oac[mi][nj][2], oac[mi][nj][3]);
        }
    }
}

// ------------------------------- launcher ----------------------------------
extern "C" void kernel_launch(void* const* d_in, const int* in_sizes, int n_in,
                              void* d_out, int out_size) {
    (void)in_sizes; (void)n_in; (void)out_size;
    const float* X   = (const float*)d_in[0];   // [8192,1024]
    const float* W   = (const float*)d_in[1];   // [8192,1024]
    const float* b   = (const float*)d_in[2];   // [8192]
    const float* lam = (const float*)d_in[3];   // [8192,16]
    float* out = (float*)d_out;                 // [8192,512]

    cudaFuncSetAttribute(somfnn_main,
                         cudaFuncAttributeMaxDynamicSharedMemorySize, SMEM_BYTES);

    pack_kernel<<<8192, 256>>>(X, W);
    somfnn_main<<<512, 256, SMEM_BYTES>>>(b, lam, out);
}

// round 15
// speedup vs baseline: 1.7879x; 1.0313x over previous
#include <cuda_runtime.h>
#include <cuda_bf16.h>
#include <cstdint>
#include <cstddef>

// ---------------------------------------------------------------------------
// out[s,o] = sum_r lambda[s,r] * sigmoid( X[s,:] . W[r*512+o,:] + b[r*512+o] )
// S=8192, K=1024, R=16, O=512.
//
// bf16 HMMA (mma.sync.m16n8k16). R15 = R13 compute + R14 bulk feed.
//   CTA 128x128 (8 warps x 64x32 tiles, MMA:LDSM = 2.67), BK=64.
//   Feed: pack kernel emits PRE-SWIZZLED 16KB tile blocks; thread 0 issues
//   2 cp.async.bulk per stage into a 3-stage x 32KB mbarrier ring (96KB).
//   1 CTA/SM, grid 256 = 64 S-tiles x 4 O-tiles.
// ---------------------------------------------------------------------------

#define BM 128
#define BN 128
#define STAGES 3
#define ROWB 128                            // bytes per smem row (BK*2)
#define A_TILE 16384                        // 128 rows x 128B
#define B_TILE 16384                        // 128 rows x 128B
#define STAGE_BYTES (A_TILE + B_TILE)       // 32768
#define TILE_SMEM (STAGES * STAGE_BYTES)    // 98304
#define SMEM_BYTES (TILE_SMEM + 64)
#define NITER 256                           // 16 rules * 16 k-chunks

__device__ __align__(1024) unsigned char gXbf[16777216]; // [st][kt] 16KB blocks
__device__ __align__(1024) unsigned char gWbf[16777216]; // [ot][rule][kt] 16KB

// ------------------------------ PTX helpers --------------------------------
static __device__ __forceinline__ uint32_t smem_u32(const void* p) {
    uint32_t a;
    asm("{ .reg .u64 t; cvta.to.shared.u64 t, %1; cvt.u32.u64 %0, t; }"
        : "=r"(a) : "l"(p));
    return a;
}
static __device__ __forceinline__ void mbar_init(uint32_t m, uint32_t cnt) {
    asm volatile("mbarrier.init.shared.b64 [%0], %1;" :: "r"(m), "r"(cnt) : "memory");
}
static __device__ __forceinline__ void mbar_wait(uint32_t m, uint32_t parity) {
    asm volatile(
        "{\n\t.reg .pred P;\n\t"
        "W_%=:\n\t"
        "mbarrier.try_wait.parity.acquire.cta.shared::cta.b64 P, [%0], %1, 0x989680;\n\t"
        "@!P bra W_%=;\n\t}"
        :: "r"(m), "r"(parity) : "memory");
}
static __device__ __forceinline__ void mbar_arrive(uint32_t m) {
    asm volatile("mbarrier.arrive.shared.b64 _, [%0];" :: "r"(m) : "memory");
}
static __device__ __forceinline__ void mbar_expect_tx(uint32_t m, uint32_t bytes) {
    asm volatile("mbarrier.arrive.expect_tx.shared.b64 _, [%0], %1;"
                 :: "r"(m), "r"(bytes) : "memory");
}
static __device__ __forceinline__ void bulk_g2s(uint32_t dst, const void* src,
                                                uint32_t bytes, uint32_t mbar) {
    asm volatile(
        "cp.async.bulk.shared::cluster.global.mbarrier::complete_tx::bytes "
        "[%0], [%1], %2, [%3];"
        :: "r"(dst), "l"(src), "r"(bytes), "r"(mbar) : "memory");
}
#define FENCE_PA() asm volatile("fence.proxy.async.shared::cta;" ::: "memory")

static __device__ __forceinline__ void ldsm4(uint32_t& r0, uint32_t& r1,
                                             uint32_t& r2, uint32_t& r3,
                                             uint32_t addr) {
    asm volatile("ldmatrix.sync.aligned.m8n8.x4.shared.b16 {%0,%1,%2,%3}, [%4];"
                 : "=r"(r0), "=r"(r1), "=r"(r2), "=r"(r3) : "r"(addr));
}
static __device__ __forceinline__ void mma16816(
    float& c0, float& c1, float& c2, float& c3,
    uint32_t a0, uint32_t a1, uint32_t a2, uint32_t a3,
    uint32_t b0, uint32_t b1) {
    asm volatile(
        "mma.sync.aligned.m16n8k16.row.col.f32.bf16.bf16.f32 "
        "{%0,%1,%2,%3}, {%4,%5,%6,%7}, {%8,%9}, {%0,%1,%2,%3};"
        : "+f"(c0), "+f"(c1), "+f"(c2), "+f"(c3)
        : "r"(a0), "r"(a1), "r"(a2), "r"(a3), "r"(b0), "r"(b1));
}

// --------------- pack: fp32 -> bf16, tiled + PRE-SWIZZLED ------------------
__global__ void pack_kernel(const float* __restrict__ X,
                            const float* __restrict__ W) {
    unsigned q = blockIdx.x * blockDim.x + threadIdx.x;   // 2^21 threads exactly
    const float* src;
    unsigned char* dst;
    if (q < (1u << 20)) {
        // X: q = [st(6)][kt(4)][row(7)][g(3)]
        unsigned g   = q & 7;
        unsigned row = (q >> 3) & 127;
        unsigned kt  = (q >> 10) & 15;
        unsigned st  = q >> 14;
        src = X + ((size_t)(st * 128 + row) * 1024 + kt * 64 + g * 8);
        dst = gXbf + (size_t)(st * 16 + kt) * A_TILE
                   + row * 128 + ((g ^ (row & 7)) << 4);
    } else {
        // W: p = [ot(2)][rule(4)][kt(4)][row(7)][g(3)]
        unsigned p    = q - (1u << 20);
        unsigned g    = p & 7;
        unsigned row  = (p >> 3) & 127;
        unsigned kt   = (p >> 10) & 15;
        unsigned rule = (p >> 14) & 15;
        unsigned ot   = p >> 18;
        src = W + ((size_t)(rule * 512 + ot * 128 + row) * 1024 + kt * 64 + g * 8);
        dst = gWbf + (size_t)((ot * 16 + rule) * 16 + kt) * B_TILE
                   + row * 128 + ((g ^ (row & 7)) << 4);
    }
    float4 v0 = ((const float4*)src)[0];
    float4 v1 = ((const float4*)src)[1];
    __nv_bfloat162 b0 = __floats2bfloat162_rn(v0.x, v0.y);
    __nv_bfloat162 b1 = __floats2bfloat162_rn(v0.z, v0.w);
    __nv_bfloat162 b2 = __floats2bfloat162_rn(v1.x, v1.y);
    __nv_bfloat162 b3 = __floats2bfloat162_rn(v1.z, v1.w);
    uint4 o;
    o.x = *reinterpret_cast<unsigned*>(&b0);
    o.y = *reinterpret_cast<unsigned*>(&b1);
    o.z = *reinterpret_cast<unsigned*>(&b2);
    o.w = *reinterpret_cast<unsigned*>(&b3);
    *reinterpret_cast<uint4*>(dst) = o;
}

// ------------------------------- main kernel -------------------------------
__global__ void __launch_bounds__(256, 1) somfnn_main(
    const float* __restrict__ bias,      // [8192] = [16 rules x 512]
    const float* __restrict__ lambdas,   // [8192 x 16]
    float* __restrict__ out)             // [8192 x 512]
{
    extern __shared__ __align__(128) unsigned char smem[];
    const uint32_t sb = smem_u32(smem);
    const uint32_t mb = sb + TILE_SMEM;      // full[s]=mb+8s, empty[s]=mb+24+8s

    const int tid  = threadIdx.x;
    const int lane = tid & 31;
    const int wid  = tid >> 5;           // 0..7
    const int st   = blockIdx.x >> 2;    // S-tile 0..63
    const int ot   = blockIdx.x & 3;     // O-tile 0..3
    const int wm   = wid >> 2;           // 0..1 -> rows wm*64
    const int wn   = wid & 3;            // 0..3 -> cols wn*32

    if (tid == 0) {
#pragma unroll
        for (int s = 0; s < STAGES; s++) {
            mbar_init(mb + 8 * s, 1);          // full: expect_tx-driven
            mbar_init(mb + 24 + 8 * s, 256);   // empty: all threads arrive
        }
        FENCE_PA();
    }
    __syncthreads();

    const unsigned char* aBase = gXbf + (size_t)st * 16 * A_TILE;
    const unsigned char* bBase = gWbf + (size_t)(ot * 16) * 16 * B_TILE;

    // ---- prologue: thread 0 fills stages 0,1 (itL = 0,1 -> rule 0, kt) ----
    if (tid == 0) {
#pragma unroll
        for (int i = 0; i < 2; i++) {
            mbar_expect_tx(mb + 8 * i, STAGE_BYTES);
            bulk_g2s(sb + i * STAGE_BYTES,          aBase + (size_t)i * A_TILE,
                     A_TILE, mb + 8 * i);
            bulk_g2s(sb + i * STAGE_BYTES + A_TILE, bBase + (size_t)i * B_TILE,
                     B_TILE, mb + 8 * i);
        }
    }

    // ---- ldmatrix per-lane invariants (R13-proven formulas) ----
    const int laneLo = lane & 15;
    const int laneHi = lane >> 4;
    const uint32_t aRow = (uint32_t)(wm * 64 + laneLo);
    const uint32_t aOff = aRow * ROWB;
    const uint32_t sA   = aRow & 7;
    const uint32_t bRow = (uint32_t)(wn * 32 + ((lane >> 4) << 3) + (lane & 7));
    const uint32_t bOff = bRow * ROWB;
    const uint32_t sB   = bRow & 7;
    const uint32_t bCLo = (uint32_t)((lane >> 3) & 1);

    float acc[4][4][4];   // current-rule accumulators (warp tile 64x32)
    float oac[4][4][4];   // lambda-weighted output accumulators
#pragma unroll
    for (int mi = 0; mi < 4; mi++)
#pragma unroll
        for (int nj = 0; nj < 4; nj++)
#pragma unroll
            for (int q = 0; q < 4; q++) { acc[mi][nj][q] = 0.f; oac[mi][nj][q] = 0.f; }

    const int rowL = lane >> 2;
    const int colL = 2 * (lane & 3);

    int cs = 0, cpar = 0;    // consumer ring cursor
#pragma unroll 1
    for (int it = 0; it < NITER; it++) {
        // ---- producer: thread 0 refills slot for itL = it+2 ----
        if (tid == 0 && it + 2 < NITER) {
            const int itL  = it + 2;
            const int pass = itL / 3;
            const int s    = itL - pass * 3;
            if (pass > 0) mbar_wait(mb + 24 + 8 * s, (uint32_t)((pass - 1) & 1));
            mbar_expect_tx(mb + 8 * s, STAGE_BYTES);
            const int rule = itL >> 4;
            const int kt   = itL & 15;
            bulk_g2s(sb + s * STAGE_BYTES,
                     aBase + (size_t)kt * A_TILE, A_TILE, mb + 8 * s);
            bulk_g2s(sb + s * STAGE_BYTES + A_TILE,
                     bBase + (size_t)(rule * 16 + kt) * B_TILE, B_TILE, mb + 8 * s);
        }

        // ---- consumer: wait for slot cs, compute ----
        mbar_wait(mb + 8 * cs, (uint32_t)cpar);

        const uint32_t As = sb + (uint32_t)cs * STAGE_BYTES;
        const uint32_t Bs = As + A_TILE;

#pragma unroll
        for (int ks = 0; ks < 4; ks++) {
            uint32_t a[4][4];
#pragma unroll
            for (int mi = 0; mi < 4; mi++) {
                const uint32_t addr = As + aOff + (uint32_t)(mi * 16 * ROWB)
                                    + (((uint32_t)(ks * 2 + laneHi) ^ sA) * 16u);
                ldsm4(a[mi][0], a[mi][1], a[mi][2], a[mi][3], addr);
            }
            uint32_t b[4][2];
#pragma unroll
            for (int nh = 0; nh < 2; nh++) {
                const uint32_t addr = Bs + bOff + (uint32_t)(nh * 16 * ROWB)
                                    + ((((uint32_t)(ks * 2) + bCLo) ^ sB) * 16u);
                uint32_t r0, r1, r2, r3;
                ldsm4(r0, r1, r2, r3, addr);
                b[nh * 2][0] = r0;     b[nh * 2][1] = r1;
                b[nh * 2 + 1][0] = r2; b[nh * 2 + 1][1] = r3;
            }
#pragma unroll
            for (int mi = 0; mi < 4; mi++)
#pragma unroll
                for (int nj = 0; nj < 4; nj++)
                    mma16816(acc[mi][nj][0], acc[mi][nj][1],
                             acc[mi][nj][2], acc[mi][nj][3],
                             a[mi][0], a[mi][1], a[mi][2], a[mi][3],
                             b[nj][0], b[nj][1]);
        }

        // slot consumed
        mbar_arrive(mb + 24 + 8 * cs);
        if (++cs == STAGES) { cs = 0; cpar ^= 1; }

        // ---- per-rule epilogue: sigmoid + lambda-weighted accumulate ----
        if ((it & 15) == 15) {
            const int r = it >> 4;
#pragma unroll
            for (int mi = 0; mi < 4; mi++) {
                const int r0g = st * 128 + wm * 64 + mi * 16 + rowL;
                const float l0 = __ldg(lambdas + (size_t)r0g * 16 + r);
                const float l1 = __ldg(lambdas + (size_t)(r0g + 8) * 16 + r);
#pragma unroll
                for (int nj = 0; nj < 4; nj++) {
                    const int col = ot * 128 + wn * 32 + nj * 8 + colL;
                    const float2 bb = *reinterpret_cast<const float2*>(
                        bias + r * 512 + col);
                    float z0 = acc[mi][nj][0] + bb.x;
                    float z1 = acc[mi][nj][1] + bb.y;
                    float z2 = acc[mi][nj][2] + bb.x;
                    float z3 = acc[mi][nj][3] + bb.y;
                    float s0 = __fdividef(1.f, 1.f + __expf(-z0));
                    float s1 = __fdividef(1.f, 1.f + __expf(-z1));
                    float s2 = __fdividef(1.f, 1.f + __expf(-z2));
                    float s3 = __fdividef(1.f, 1.f + __expf(-z3));
                    oac[mi][nj][0] = fmaf(l0, s0, oac[mi][nj][0]);
                    oac[mi][nj][1] = fmaf(l0, s1, oac[mi][nj][1]);
                    oac[mi][nj][2] = fmaf(l1, s2, oac[mi][nj][2]);
                    oac[mi][nj][3] = fmaf(l1, s3, oac[mi][nj][3]);
                    acc[mi][nj][0] = 0.f; acc[mi][nj][1] = 0.f;
                    acc[mi][nj][2] = 0.f; acc[mi][nj][3] = 0.f;
                }
            }
        }
    }

    // ---- final store: out tile [128 x 128] fp32 ----
#pragma unroll
    for (int mi = 0; mi < 4; mi++) {
        const int r0g = st * 128 + wm * 64 + mi * 16 + rowL;
#pragma unroll
        for (int nj = 0; nj < 4; nj++) {
            const int col = ot * 128 + wn * 32 + nj * 8 + colL;
            *reinterpret_cast<float2*>(out + (size_t)r0g * 512 + col) =
                make_float2(oac[mi][nj][0], oac[mi][nj][1]);
            *reinterpret_cast<float2*>(out + (size_t)(r0g + 8) * 512 + col) =
                make_float2(oac[mi][nj][2], oac[mi][nj][3]);
        }
    }
}

// ------------------------------- launcher ----------------------------------
extern "C" void kernel_launch(void* const* d_in, const int* in_sizes, int n_in,
                              void* d_out, int out_size) {
    (void)in_sizes; (void)n_in; (void)out_size;
    const float* X   = (const float*)d_in[0];   // [8192,1024]
    const float* W   = (const float*)d_in[1];   // [8192,1024]
    const float* b   = (const float*)d_in[2];   // [8192]
    const float* lam = (const float*)d_in[3];   // [8192,16]
    float* out = (float*)d_out;                 // [8192,512]

    cudaFuncSetAttribute(somfnn_main,
                         cudaFuncAttributeMaxDynamicSharedMemorySize, SMEM_BYTES);

    pack_kernel<<<8192, 256>>>(X, W);
    somfnn_main<<<256, 256, SMEM_BYTES>>>(b, lam, out);
}

// round 17
// speedup vs baseline: 1.9026x; 1.0641x over previous
#include <cuda_runtime.h>
#include <cuda_bf16.h>
#include <cstdint>
#include <cstddef>

// ---------------------------------------------------------------------------
// out[s,o] = sum_r lambda[s,r] * sigmoid( X[s,:] . W[r*512+o,:] + b[r*512+o] )
// S=8192, K=1024, R=16, O=512.
//
// bf16 HMMA (mma.sync.m16n8k16). R16 = R15 with BK=128 stages.
//   CTA 128x128 (8 warps x 64x32 tiles), BK=128 per stage (ks 0..7).
//   Feed: pack kernel emits PRE-SWIZZLED 32KB tile blocks; thread 0 issues
//   2 cp.async.bulk per stage into a 3-stage x 64KB mbarrier ring (192KB).
//   NITER = 128 (halved per-iter sync/refill overhead vs R15).
//   1 CTA/SM, grid 256 = 64 S-tiles x 4 O-tiles.
// ---------------------------------------------------------------------------

#define BM 128
#define BN 128
#define STAGES 3
#define ROWB 256                            // bytes per smem row (BK*2)
#define A_TILE 32768                        // 128 rows x 256B
#define B_TILE 32768                        // 128 rows x 256B
#define STAGE_BYTES (A_TILE + B_TILE)       // 65536
#define TILE_SMEM (STAGES * STAGE_BYTES)    // 196608
#define SMEM_BYTES (TILE_SMEM + 64)
#define NITER 128                           // 16 rules * 8 k-chunks(128)

__device__ __align__(1024) unsigned char gXbf[16777216]; // [st][kt2] 32KB blocks
__device__ __align__(1024) unsigned char gWbf[16777216]; // [ot][rule][kt2] 32KB

// ------------------------------ PTX helpers --------------------------------
static __device__ __forceinline__ uint32_t smem_u32(const void* p) {
    uint32_t a;
    asm("{ .reg .u64 t; cvta.to.shared.u64 t, %1; cvt.u32.u64 %0, t; }"
        : "=r"(a) : "l"(p));
    return a;
}
static __device__ __forceinline__ void mbar_init(uint32_t m, uint32_t cnt) {
    asm volatile("mbarrier.init.shared.b64 [%0], %1;" :: "r"(m), "r"(cnt) : "memory");
}
static __device__ __forceinline__ void mbar_wait(uint32_t m, uint32_t parity) {
    asm volatile(
        "{\n\t.reg .pred P;\n\t"
        "W_%=:\n\t"
        "mbarrier.try_wait.parity.acquire.cta.shared::cta.b64 P, [%0], %1, 0x989680;\n\t"
        "@!P bra W_%=;\n\t}"
        :: "r"(m), "r"(parity) : "memory");
}
static __device__ __forceinline__ void mbar_arrive(uint32_t m) {
    asm volatile("mbarrier.arrive.shared.b64 _, [%0];" :: "r"(m) : "memory");
}
static __device__ __forceinline__ void mbar_expect_tx(uint32_t m, uint32_t bytes) {
    asm volatile("mbarrier.arrive.expect_tx.shared.b64 _, [%0], %1;"
                 :: "r"(m), "r"(bytes) : "memory");
}
static __device__ __forceinline__ void bulk_g2s(uint32_t dst, const void* src,
                                                uint32_t bytes, uint32_t mbar) {
    asm volatile(
        "cp.async.bulk.shared::cluster.global.mbarrier::complete_tx::bytes "
        "[%0], [%1], %2, [%3];"
        :: "r"(dst), "l"(src), "r"(bytes), "r"(mbar) : "memory");
}
#define FENCE_PA() asm volatile("fence.proxy.async.shared::cta;" ::: "memory")

static __device__ __forceinline__ void ldsm4(uint32_t& r0, uint32_t& r1,
                                             uint32_t& r2, uint32_t& r3,
                                             uint32_t addr) {
    asm volatile("ldmatrix.sync.aligned.m8n8.x4.shared.b16 {%0,%1,%2,%3}, [%4];"
                 : "=r"(r0), "=r"(r1), "=r"(r2), "=r"(r3) : "r"(addr));
}
static __device__ __forceinline__ void mma16816(
    float& c0, float& c1, float& c2, float& c3,
    uint32_t a0, uint32_t a1, uint32_t a2, uint32_t a3,
    uint32_t b0, uint32_t b1) {
    asm volatile(
        "mma.sync.aligned.m16n8k16.row.col.f32.bf16.bf16.f32 "
        "{%0,%1,%2,%3}, {%4,%5,%6,%7}, {%8,%9}, {%0,%1,%2,%3};"
        : "+f"(c0), "+f"(c1), "+f"(c2), "+f"(c3)
        : "r"(a0), "r"(a1), "r"(a2), "r"(a3), "r"(b0), "r"(b1));
}

// --------------- pack: fp32 -> bf16, tiled + PRE-SWIZZLED ------------------
__global__ void pack_kernel(const float* __restrict__ X,
                            const float* __restrict__ W) {
    unsigned q = blockIdx.x * blockDim.x + threadIdx.x;   // 2^21 threads exactly
    const float* src;
    unsigned char* dst;
    if (q < (1u << 20)) {
        // X: q = [st(6)][kt2(3)][row(7)][g(4)]
        unsigned g   = q & 15;
        unsigned row = (q >> 4) & 127;
        unsigned kt2 = (q >> 11) & 7;
        unsigned st  = q >> 14;
        src = X + ((size_t)(st * 128 + row) * 1024 + kt2 * 128 + g * 8);
        dst = gXbf + (size_t)(st * 8 + kt2) * A_TILE
                   + row * 256 + ((g ^ (row & 7)) << 4);
    } else {
        // W: p = [ot(2)][rule(4)][kt2(3)][row(7)][g(4)]
        unsigned p    = q - (1u << 20);
        unsigned g    = p & 15;
        unsigned row  = (p >> 4) & 127;
        unsigned kt2  = (p >> 11) & 7;
        unsigned rule = (p >> 14) & 15;
        unsigned ot   = p >> 18;
        src = W + ((size_t)(rule * 512 + ot * 128 + row) * 1024 + kt2 * 128 + g * 8);
        dst = gWbf + (size_t)((ot * 16 + rule) * 8 + kt2) * B_TILE
                   + row * 256 + ((g ^ (row & 7)) << 4);
    }
    float4 v0 = ((const float4*)src)[0];
    float4 v1 = ((const float4*)src)[1];
    __nv_bfloat162 b0 = __floats2bfloat162_rn(v0.x, v0.y);
    __nv_bfloat162 b1 = __floats2bfloat162_rn(v0.z, v0.w);
    __nv_bfloat162 b2 = __floats2bfloat162_rn(v1.x, v1.y);
    __nv_bfloat162 b3 = __floats2bfloat162_rn(v1.z, v1.w);
    uint4 o;
    o.x = *reinterpret_cast<unsigned*>(&b0);
    o.y = *reinterpret_cast<unsigned*>(&b1);
    o.z = *reinterpret_cast<unsigned*>(&b2);
    o.w = *reinterpret_cast<unsigned*>(&b3);
    *reinterpret_cast<uint4*>(dst) = o;
}

// ------------------------------- main kernel -------------------------------
__global__ void __launch_bounds__(256, 1) somfnn_main(
    const float* __restrict__ bias,      // [8192] = [16 rules x 512]
    const float* __restrict__ lambdas,   // [8192 x 16]
    float* __restrict__ out)             // [8192 x 512]
{
    extern __shared__ __align__(128) unsigned char smem[];
    const uint32_t sb = smem_u32(smem);
    const uint32_t mb = sb + TILE_SMEM;      // full[s]=mb+8s, empty[s]=mb+24+8s

    const int tid  = threadIdx.x;
    const int lane = tid & 31;
    const int wid  = tid >> 5;           // 0..7
    const int st   = blockIdx.x >> 2;    // S-tile 0..63
    const int ot   = blockIdx.x & 3;     // O-tile 0..3
    const int wm   = wid >> 2;           // 0..1 -> rows wm*64
    const int wn   = wid & 3;            // 0..3 -> cols wn*32

    if (tid == 0) {
#pragma unroll
        for (int s = 0; s < STAGES; s++) {
            mbar_init(mb + 8 * s, 1);          // full: expect_tx-driven
            mbar_init(mb + 24 + 8 * s, 256);   // empty: all threads arrive
        }
        FENCE_PA();
    }
    __syncthreads();

    const unsigned char* aBase = gXbf + (size_t)st * 8 * A_TILE;
    const unsigned char* bBase = gWbf + (size_t)(ot * 16) * 8 * B_TILE;

    // ---- prologue: thread 0 fills stages 0,1 (itL = 0,1 -> rule 0, kt2) ----
    if (tid == 0) {
#pragma unroll
        for (int i = 0; i < 2; i++) {
            mbar_expect_tx(mb + 8 * i, STAGE_BYTES);
            bulk_g2s(sb + i * STAGE_BYTES,          aBase + (size_t)i * A_TILE,
                     A_TILE, mb + 8 * i);
            bulk_g2s(sb + i * STAGE_BYTES + A_TILE, bBase + (size_t)i * B_TILE,
                     B_TILE, mb + 8 * i);
        }
    }

    // ---- ldmatrix per-lane invariants (R8-proven ROWB=256 formulas) ----
    const int laneLo = lane & 15;
    const int laneHi = lane >> 4;
    const uint32_t aRow = (uint32_t)(wm * 64 + laneLo);
    const uint32_t aOff = aRow * ROWB;
    const uint32_t sA   = aRow & 7;
    const uint32_t bRow = (uint32_t)(wn * 32 + ((lane >> 4) << 3) + (lane & 7));
    const uint32_t bOff = bRow * ROWB;
    const uint32_t sB   = bRow & 7;
    const uint32_t bCLo = (uint32_t)((lane >> 3) & 1);

    float acc[4][4][4];   // current-rule accumulators (warp tile 64x32)
    float oac[4][4][4];   // lambda-weighted output accumulators
#pragma unroll
    for (int mi = 0; mi < 4; mi++)
#pragma unroll
        for (int nj = 0; nj < 4; nj++)
#pragma unroll
            for (int q = 0; q < 4; q++) { acc[mi][nj][q] = 0.f; oac[mi][nj][q] = 0.f; }

    const int rowL = lane >> 2;
    const int colL = 2 * (lane & 3);

    int cs = 0, cpar = 0;    // consumer ring cursor
#pragma unroll 1
    for (int it = 0; it < NITER; it++) {
        // ---- producer: thread 0 refills slot for itL = it+2 ----
        if (tid == 0 && it + 2 < NITER) {
            const int itL  = it + 2;
            const int pass = itL / 3;
            const int s    = itL - pass * 3;
            if (pass > 0) mbar_wait(mb + 24 + 8 * s, (uint32_t)((pass - 1) & 1));
            mbar_expect_tx(mb + 8 * s, STAGE_BYTES);
            const int rule = itL >> 3;
            const int kt2  = itL & 7;
            bulk_g2s(sb + s * STAGE_BYTES,
                     aBase + (size_t)kt2 * A_TILE, A_TILE, mb + 8 * s);
            bulk_g2s(sb + s * STAGE_BYTES + A_TILE,
                     bBase + (size_t)(rule * 8 + kt2) * B_TILE, B_TILE, mb + 8 * s);
        }

        // ---- consumer: wait for slot cs, compute ----
        mbar_wait(mb + 8 * cs, (uint32_t)cpar);

        const uint32_t As = sb + (uint32_t)cs * STAGE_BYTES;
        const uint32_t Bs = As + A_TILE;

#pragma unroll
        for (int ks = 0; ks < 8; ks++) {
            uint32_t a[4][4];
#pragma unroll
            for (int mi = 0; mi < 4; mi++) {
                const uint32_t addr = As + aOff + (uint32_t)(mi * 16 * ROWB)
                                    + (((uint32_t)(ks * 2 + laneHi) ^ sA) * 16u);
                ldsm4(a[mi][0], a[mi][1], a[mi][2], a[mi][3], addr);
            }
            uint32_t b[4][2];
#pragma unroll
            for (int nh = 0; nh < 2; nh++) {
                const uint32_t addr = Bs + bOff + (uint32_t)(nh * 16 * ROWB)
                                    + ((((uint32_t)(ks * 2) + bCLo) ^ sB) * 16u);
                uint32_t r0, r1, r2, r3;
                ldsm4(r0, r1, r2, r3, addr);
                b[nh * 2][0] = r0;     b[nh * 2][1] = r1;
                b[nh * 2 + 1][0] = r2; b[nh * 2 + 1][1] = r3;
            }
#pragma unroll
            for (int mi = 0; mi < 4; mi++)
#pragma unroll
                for (int nj = 0; nj < 4; nj++)
                    mma16816(acc[mi][nj][0], acc[mi][nj][1],
                             acc[mi][nj][2], acc[mi][nj][3],
                             a[mi][0], a[mi][1], a[mi][2], a[mi][3],
                             b[nj][0], b[nj][1]);
        }

        // slot consumed
        mbar_arrive(mb + 24 + 8 * cs);
        if (++cs == STAGES) { cs = 0; cpar ^= 1; }

        // ---- per-rule epilogue: sigmoid + lambda-weighted accumulate ----
        if ((it & 7) == 7) {
            const int r = it >> 3;
#pragma unroll
            for (int mi = 0; mi < 4; mi++) {
                const int r0g = st * 128 + wm * 64 + mi * 16 + rowL;
                const float l0 = __ldg(lambdas + (size_t)r0g * 16 + r);
                const float l1 = __ldg(lambdas + (size_t)(r0g + 8) * 16 + r);
#pragma unroll
                for (int nj = 0; nj < 4; nj++) {
                    const int col = ot * 128 + wn * 32 + nj * 8 + colL;
                    const float2 bb = *reinterpret_cast<const float2*>(
                        bias + r * 512 + col);
                    float z0 = acc[mi][nj][0] + bb.x;
                    float z1 = acc[mi][nj][1] + bb.y;
                    float z2 = acc[mi][nj][2] + bb.x;
                    float z3 = acc[mi][nj][3] + bb.y;
                    float s0 = __fdividef(1.f, 1.f + __expf(-z0));
                    float s1 = __fdividef(1.f, 1.f + __expf(-z1));
                    float s2 = __fdividef(1.f, 1.f + __expf(-z2));
                    float s3 = __fdividef(1.f, 1.f + __expf(-z3));
                    oac[mi][nj][0] = fmaf(l0, s0, oac[mi][nj][0]);
                    oac[mi][nj][1] = fmaf(l0, s1, oac[mi][nj][1]);
                    oac[mi][nj][2] = fmaf(l1, s2, oac[mi][nj][2]);
                    oac[mi][nj][3] = fmaf(l1, s3, oac[mi][nj][3]);
                    acc[mi][nj][0] = 0.f; acc[mi][nj][1] = 0.f;
                    acc[mi][nj][2] = 0.f; acc[mi][nj][3] = 0.f;
                }
            }
        }
    }

    // ---- final store: out tile [128 x 128] fp32 ----
#pragma unroll
    for (int mi = 0; mi < 4; mi++) {
        const int r0g = st * 128 + wm * 64 + mi * 16 + rowL;
#pragma unroll
        for (int nj = 0; nj < 4; nj++) {
            const int col = ot * 128 + wn * 32 + nj * 8 + colL;
            *reinterpret_cast<float2*>(out + (size_t)r0g * 512 + col) =
                make_float2(oac[mi][nj][0], oac[mi][nj][1]);
            *reinterpret_cast<float2*>(out + (size_t)(r0g + 8) * 512 + col) =
                make_float2(oac[mi][nj][2], oac[mi][nj][3]);
        }
    }
}

// ------------------------------- launcher ----------------------------------
extern "C" void kernel_launch(void* const* d_in, const int* in_sizes, int n_in,
                              void* d_out, int out_size) {
    (void)in_sizes; (void)n_in; (void)out_size;
    const float* X   = (const float*)d_in[0];   // [8192,1024]
    const float* W   = (const float*)d_in[1];   // [8192,1024]
    const float* b   = (const float*)d_in[2];   // [8192]
    const float* lam = (const float*)d_in[3];   // [8192,16]
    float* out = (float*)d_out;                 // [8192,512]

    cudaFuncSetAttribute(somfnn_main,
                         cudaFuncAttributeMaxDynamicSharedMemorySize, SMEM_BYTES);

    pack_kernel<<<8192, 256>>>(X, W);
    somfnn_main<<<256, 256, SMEM_BYTES>>>(b, lam, out);
}